// round 1
// baseline (speedup 1.0000x reference)
#include <cuda_runtime.h>

#define Bb 256
#define Tt 512
#define Cc 256
#define Ll 64
#define Ss 129            // 2*L+1 extended states
#define NU 65             // unique classes per row: blank + 64 labels
#define GSTR 68           // padded stride of gather buffer
#define TPAD 520          // padded T so prefetch can read past the end
#define LOG2E 1.4426950408889634f
#define LN2   0.6931471805599453f
#define NEG2  (-1.442695e30f)   // -1e30 nats expressed in log2 units

// scratch (static device globals: allocation-free)
__device__ float g_buf[(size_t)Bb * TPAD * GSTR];   // ~36 MB, fits in L2
__device__ float loss_buf[Bb];

// ---------------------------------------------------------------------------
// Kernel 1: per-(b,t) log-softmax denominator + gather of the 65 needed
// classes into compact log2-domain buffer. Warp per row, 8 rows per block.
// ---------------------------------------------------------------------------
__global__ void k_lse_gather(const float* __restrict__ logits,
                             const int* __restrict__ targets) {
    int b    = blockIdx.y;
    int warp = threadIdx.x >> 5;
    int lane = threadIdx.x & 31;

    __shared__ int lab[NU];
    if (threadIdx.x == 0) lab[0] = 0;                         // blank
    if (threadIdx.x < Ll) lab[threadIdx.x + 1] = targets[b * Ll + threadIdx.x];
    __syncthreads();

    int t = blockIdx.x * 8 + warp;
    const float* row = logits + ((size_t)b * Tt + t) * Cc;
    const float4* r4 = (const float4*)row;
    float4 v0 = r4[lane];
    float4 v1 = r4[lane + 32];

    float m = fmaxf(fmaxf(fmaxf(v0.x, v0.y), fmaxf(v0.z, v0.w)),
                    fmaxf(fmaxf(v1.x, v1.y), fmaxf(v1.z, v1.w)));
#pragma unroll
    for (int o = 16; o; o >>= 1) m = fmaxf(m, __shfl_xor_sync(0xffffffffu, m, o));

    float m2 = m * LOG2E;
    float ss = exp2f(fmaf(v0.x, LOG2E, -m2)) + exp2f(fmaf(v0.y, LOG2E, -m2))
             + exp2f(fmaf(v0.z, LOG2E, -m2)) + exp2f(fmaf(v0.w, LOG2E, -m2))
             + exp2f(fmaf(v1.x, LOG2E, -m2)) + exp2f(fmaf(v1.y, LOG2E, -m2))
             + exp2f(fmaf(v1.z, LOG2E, -m2)) + exp2f(fmaf(v1.w, LOG2E, -m2));
#pragma unroll
    for (int o = 16; o; o >>= 1) ss += __shfl_xor_sync(0xffffffffu, ss, o);

    float lse2 = m2 + log2f(ss);   // log2(sum exp(x))

    float* grow = g_buf + ((size_t)b * TPAD + t) * GSTR;
#pragma unroll
    for (int u = lane; u < NU; u += 32)
        grow[u] = fmaf(row[lab[u]], LOG2E, -lse2);   // L1-hit gather (row just read)
}

// ---------------------------------------------------------------------------
// Kernel 2: forward recursion. One block per batch row, 160 threads,
// one extended state per thread, double-buffered alpha in smem (1 bar/step),
// lp prefetched 4 timesteps ahead in a static register ring.
// ---------------------------------------------------------------------------
__global__ void __launch_bounds__(160, 8)
k_ctc(const int* __restrict__ targets,
      const int* __restrict__ in_len,
      const int* __restrict__ tgt_len) {
    int b = blockIdx.x;
    int s = threadIdx.x;

    __shared__ float sA[2][Ss + 2];   // +2 halo at the front (always NEG2)

    const float* grow = g_buf + (size_t)b * TPAD * GSTR;

    for (int i = threadIdx.x; i < 2 * (Ss + 2); i += blockDim.x)
        ((float*)sA)[i] = NEG2;

    int u = 0;
    bool skip = false;
    if (s < Ss) {
        u = (s & 1) ? ((s >> 1) + 1) : 0;      // gather-buffer column for this state
        if ((s & 1) && s >= 3)                  // odd (non-blank) states past s=1
            skip = (targets[b * Ll + u - 1] != targets[b * Ll + u - 2]);
    }
    __syncthreads();
    if (s == 0) sA[0][2] = grow[0];             // alpha0[0] = lp(t=0, blank)
    if (s == 1) sA[0][3] = grow[1];             // alpha0[1] = lp(t=0, y1)
    __syncthreads();

    int Ti = in_len[b];
    if (Ti > Tt) Ti = Tt;

    int p = 0;
    const float* gp = grow + u;                  // per-thread lp column base
    float lp0 = gp[1 * GSTR], lp1 = gp[2 * GSTR],
          lp2 = gp[3 * GSTR], lp3 = gp[4 * GSTR];

#define STEP(LPREG, TLD) do {                                            \
        float lpv = LPREG;                                               \
        LPREG = gp[(TLD) * GSTR];          /* prefetch t+4 (padded) */   \
        if (s < Ss) {                                                    \
            float a1 = sA[p][s + 2];                                     \
            float a2 = sA[p][s + 1];                                     \
            float a3 = skip ? sA[p][s] : NEG2;                           \
            float mm = fmaxf(fmaxf(a1, a2), a3);                         \
            float r  = exp2f(a1 - mm) + exp2f(a2 - mm) + exp2f(a3 - mm); \
            float nv = mm + log2f(r) + lpv;                              \
            sA[p ^ 1][s + 2] = fmaxf(nv, NEG2);                          \
        }                                                                \
        __syncthreads();                                                 \
        p ^= 1;                                                          \
    } while (0)

    int t = 1;
    for (; t + 3 < Ti; t += 4) {
        STEP(lp0, t + 4);
        STEP(lp1, t + 5);
        STEP(lp2, t + 6);
        STEP(lp3, t + 7);
    }
    if (t < Ti) { STEP(lp0, t + 4); t++; }
    if (t < Ti) { STEP(lp1, t + 4); t++; }
    if (t < Ti) { STEP(lp2, t + 4); t++; }
#undef STEP

    if (s == 0) {
        int tl   = tgt_len[b];
        float bl = sA[p][2 * tl + 2];
        float bp = sA[p][2 * tl + 1];
        float mm = fmaxf(bl, bp);
        float l2 = mm + log2f(exp2f(bl - mm) + exp2f(bp - mm));
        float loss = -l2 * LN2;                 // back to nats
        if (loss > 1e20f) loss = 0.0f;          // zero_infinity
        loss_buf[b] = loss / (float)tl;
    }
}

// ---------------------------------------------------------------------------
// Kernel 3: deterministic mean over B=256 (no atomics).
// ---------------------------------------------------------------------------
__global__ void k_reduce(float* __restrict__ out) {
    int i = threadIdx.x;
    float v = loss_buf[i];
#pragma unroll
    for (int o = 16; o; o >>= 1) v += __shfl_xor_sync(0xffffffffu, v, o);
    __shared__ float ws[8];
    if ((i & 31) == 0) ws[i >> 5] = v;
    __syncthreads();
    if (i == 0) {
        float sum = 0.f;
#pragma unroll
        for (int w = 0; w < 8; w++) sum += ws[w];
        out[0] = sum * (1.0f / (float)Bb);
    }
}

extern "C" void kernel_launch(void* const* d_in, const int* in_sizes, int n_in,
                              void* d_out, int out_size) {
    const float* logits  = (const float*)d_in[0];
    const int*   targets = (const int*)d_in[1];
    const int*   in_len  = (const int*)d_in[2];
    const int*   tgt_len = (const int*)d_in[3];
    float* out = (float*)d_out;

    k_lse_gather<<<dim3(Tt / 8, Bb), 256>>>(logits, targets);
    k_ctc<<<Bb, 160>>>(targets, in_len, tgt_len);
    k_reduce<<<1, 256>>>(out);
}

// round 4
// speedup vs baseline: 1.1342x; 1.1342x over previous
#include <cuda_runtime.h>

#define Bb 256
#define Tt 512
#define Cc 256
#define Ll 64
#define Ss 129            // 2*L+1 extended states
#define NU 65             // unique classes per row: blank + 64 labels
#define GSTR 68           // padded stride of gather buffer
#define TPAD 520          // padded T so prefetch can read past the end
#define LOG2E 1.4426950408889634f
#define LN2   0.6931471805599453f
#define NEG2  (-1.442695e30f)   // -1e30 nats expressed in log2 units

// Hardware MUFU ops — one SASS instruction each, independent of -use_fast_math
__device__ __forceinline__ float ex2(float x) {
    float r; asm("ex2.approx.ftz.f32 %0, %1;" : "=f"(r) : "f"(x)); return r;
}
__device__ __forceinline__ float lg2(float x) {
    float r; asm("lg2.approx.ftz.f32 %0, %1;" : "=f"(r) : "f"(x)); return r;
}

// scratch (static device globals: allocation-free)
__device__ float g_buf[(size_t)Bb * TPAD * GSTR];   // ~36 MB, fits in L2
__device__ float loss_buf[Bb];

// ---------------------------------------------------------------------------
// Kernel 1: per-(b,t) log-softmax denominator + gather of the 65 needed
// classes into compact log2-domain buffer. Warp per row, 8 rows per block.
// ---------------------------------------------------------------------------
__global__ void k_lse_gather(const float* __restrict__ logits,
                             const int* __restrict__ targets) {
    int b    = blockIdx.y;
    int warp = threadIdx.x >> 5;
    int lane = threadIdx.x & 31;

    __shared__ int lab[NU];
    if (threadIdx.x == 0) lab[0] = 0;                         // blank
    if (threadIdx.x < Ll) lab[threadIdx.x + 1] = targets[b * Ll + threadIdx.x];
    __syncthreads();

    int t = blockIdx.x * 8 + warp;
    const float* row = logits + ((size_t)b * Tt + t) * Cc;
    const float4* r4 = (const float4*)row;
    float4 v0 = r4[lane];
    float4 v1 = r4[lane + 32];

    float m = fmaxf(fmaxf(fmaxf(v0.x, v0.y), fmaxf(v0.z, v0.w)),
                    fmaxf(fmaxf(v1.x, v1.y), fmaxf(v1.z, v1.w)));
#pragma unroll
    for (int o = 16; o; o >>= 1) m = fmaxf(m, __shfl_xor_sync(0xffffffffu, m, o));

    float m2 = m * LOG2E;
    float ss = ex2(fmaf(v0.x, LOG2E, -m2)) + ex2(fmaf(v0.y, LOG2E, -m2))
             + ex2(fmaf(v0.z, LOG2E, -m2)) + ex2(fmaf(v0.w, LOG2E, -m2))
             + ex2(fmaf(v1.x, LOG2E, -m2)) + ex2(fmaf(v1.y, LOG2E, -m2))
             + ex2(fmaf(v1.z, LOG2E, -m2)) + ex2(fmaf(v1.w, LOG2E, -m2));
#pragma unroll
    for (int o = 16; o; o >>= 1) ss += __shfl_xor_sync(0xffffffffu, ss, o);

    float lse2 = m2 + lg2(ss);   // log2(sum exp(x))

    float* grow = g_buf + ((size_t)b * TPAD + t) * GSTR;
#pragma unroll
    for (int u = lane; u < NU; u += 32)
        grow[u] = fmaf(row[lab[u]], LOG2E, -lse2);   // L1-hit gather (row just read)
}

// ---------------------------------------------------------------------------
// Kernel 2: forward recursion. One block per batch row, 160 threads,
// one extended state per thread, double-buffered alpha in smem (1 bar/step),
// lp prefetched 4 timesteps ahead in a static register ring. MUFU math only.
// ---------------------------------------------------------------------------
__global__ void __launch_bounds__(160, 8)
k_ctc(const int* __restrict__ targets,
      const int* __restrict__ in_len,
      const int* __restrict__ tgt_len) {
    int b = blockIdx.x;
    int s = threadIdx.x;

    __shared__ float sA[2][Ss + 2];   // +2 halo at the front (always NEG2)

    const float* grow = g_buf + (size_t)b * TPAD * GSTR;

    for (int i = threadIdx.x; i < 2 * (Ss + 2); i += blockDim.x)
        ((float*)sA)[i] = NEG2;

    int u = 0;
    bool skip = false;
    if (s < Ss) {
        u = (s & 1) ? ((s >> 1) + 1) : 0;      // gather-buffer column for this state
        if ((s & 1) && s >= 3)                  // odd (non-blank) states past s=1
            skip = (targets[b * Ll + u - 1] != targets[b * Ll + u - 2]);
    }
    __syncthreads();
    if (s == 0) sA[0][2] = grow[0];             // alpha0[0] = lp(t=0, blank)
    if (s == 1) sA[0][3] = grow[1];             // alpha0[1] = lp(t=0, y1)
    __syncthreads();

    int Ti = in_len[b];
    if (Ti > Tt) Ti = Tt;

    int p = 0;
    const float* gp = grow + u;                  // per-thread lp column base
    float lp0 = gp[1 * GSTR], lp1 = gp[2 * GSTR],
          lp2 = gp[3 * GSTR], lp3 = gp[4 * GSTR];

#define STEP(LPREG, TLD) do {                                              \
        float lpv = LPREG;                                                 \
        LPREG = gp[(TLD) * GSTR];          /* prefetch t+4 (padded) */     \
        if (s < Ss) {                                                      \
            float a1 = sA[p][s + 2];                                       \
            float a2 = sA[p][s + 1];                                       \
            float a3 = skip ? sA[p][s] : NEG2;                             \
            float mm = fmaxf(fmaxf(a1, a2), a3);                           \
            float r  = ex2(a1 - mm) + ex2(a2 - mm) + ex2(a3 - mm);         \
            float nv = mm + lg2(r) + lpv;                                  \
            sA[p ^ 1][s + 2] = fmaxf(nv, NEG2);                            \
        }                                                                  \
        __syncthreads();                                                   \
        p ^= 1;                                                            \
    } while (0)

    int t = 1;
    for (; t + 3 < Ti; t += 4) {
        STEP(lp0, t + 4);
        STEP(lp1, t + 5);
        STEP(lp2, t + 6);
        STEP(lp3, t + 7);
    }
    if (t < Ti) { STEP(lp0, t + 4); t++; }
    if (t < Ti) { STEP(lp1, t + 4); t++; }
    if (t < Ti) { STEP(lp2, t + 4); t++; }
#undef STEP

    if (s == 0) {
        int tl   = tgt_len[b];
        float bl = sA[p][2 * tl + 2];
        float bp = sA[p][2 * tl + 1];
        float mm = fmaxf(bl, bp);
        float l2 = mm + lg2(ex2(bl - mm) + ex2(bp - mm));
        float loss = -l2 * LN2;                 // back to nats
        if (loss > 1e20f) loss = 0.0f;          // zero_infinity
        loss_buf[b] = loss / (float)tl;
    }
}

// ---------------------------------------------------------------------------
// Kernel 3: deterministic mean over B=256 (no atomics).
// ---------------------------------------------------------------------------
__global__ void k_reduce(float* __restrict__ out) {
    int i = threadIdx.x;
    float v = loss_buf[i];
#pragma unroll
    for (int o = 16; o; o >>= 1) v += __shfl_xor_sync(0xffffffffu, v, o);
    __shared__ float ws[8];
    if ((i & 31) == 0) ws[i >> 5] = v;
    __syncthreads();
    if (i == 0) {
        float sum = 0.f;
#pragma unroll
        for (int w = 0; w < 8; w++) sum += ws[w];
        out[0] = sum * (1.0f / (float)Bb);
    }
}

extern "C" void kernel_launch(void* const* d_in, const int* in_sizes, int n_in,
                              void* d_out, int out_size) {
    const float* logits  = (const float*)d_in[0];
    const int*   targets = (const int*)d_in[1];
    const int*   in_len  = (const int*)d_in[2];
    const int*   tgt_len = (const int*)d_in[3];
    float* out = (float*)d_out;

    k_lse_gather<<<dim3(Tt / 8, Bb), 256>>>(logits, targets);
    k_ctc<<<Bb, 160>>>(targets, in_len, tgt_len);
    k_reduce<<<1, 256>>>(out);
}

// round 8
// speedup vs baseline: 1.6964x; 1.4956x over previous
#include <cuda_runtime.h>

#define Bb 256
#define Tt 512
#define Cc 256
#define Ll 64
#define Ss 129             // 2*L+1 extended states
#define GSTR 66            // gather row: cols 0..63 = p(labels), col 64 = p(blank)
#define TPAD 520           // padded T so prefetch can read past the end
#define LOG2E 1.4426950408889634f
#define LN2   0.6931471805599453f
#define FULLM 0xffffffffu

// Hardware MUFU ops — one SASS instruction each
__device__ __forceinline__ float ex2(float x) {
    float r; asm("ex2.approx.ftz.f32 %0, %1;" : "=f"(r) : "f"(x)); return r;
}
__device__ __forceinline__ float lg2(float x) {
    float r; asm("lg2.approx.ftz.f32 %0, %1;" : "=f"(r) : "f"(x)); return r;
}

// scratch (static device globals: allocation-free)
__device__ float g_buf[(size_t)Bb * TPAD * GSTR];   // ~35 MB
__device__ float loss_buf[Bb];

// ---------------------------------------------------------------------------
// Kernel 1: softmax probs (linear domain) of the 65 needed classes per (b,t).
// Warp handles TWO t-rows (t and t+256) for doubled MLP. 8 warps/block.
// ---------------------------------------------------------------------------
__global__ void k_lse_gather(const float* __restrict__ logits,
                             const int* __restrict__ targets) {
    int b    = blockIdx.y;
    int warp = threadIdx.x >> 5;
    int lane = threadIdx.x & 31;

    __shared__ int lab[Ll];
    if (threadIdx.x < Ll) lab[threadIdx.x] = targets[b * Ll + threadIdx.x];
    __syncthreads();

    int tA = blockIdx.x * 8 + warp;        // 0..255
    int tB = tA + 256;                     // 256..511
    const float* rowA = logits + ((size_t)b * Tt + tA) * Cc;
    const float* rowB = logits + ((size_t)b * Tt + tB) * Cc;
    const float4* rA = (const float4*)rowA;
    const float4* rB = (const float4*)rowB;
    float4 a0 = rA[lane], a1 = rA[lane + 32];   // 4 independent LDG.128 up front
    float4 b0 = rB[lane], b1 = rB[lane + 32];

    float mA = fmaxf(fmaxf(fmaxf(a0.x, a0.y), fmaxf(a0.z, a0.w)),
                     fmaxf(fmaxf(a1.x, a1.y), fmaxf(a1.z, a1.w)));
    float mB = fmaxf(fmaxf(fmaxf(b0.x, b0.y), fmaxf(b0.z, b0.w)),
                     fmaxf(fmaxf(b1.x, b1.y), fmaxf(b1.z, b1.w)));
#pragma unroll
    for (int o = 16; o; o >>= 1) {
        mA = fmaxf(mA, __shfl_xor_sync(FULLM, mA, o));
        mB = fmaxf(mB, __shfl_xor_sync(FULLM, mB, o));
    }
    float mA2 = mA * LOG2E, mB2 = mB * LOG2E;
    float sA = ex2(fmaf(a0.x, LOG2E, -mA2)) + ex2(fmaf(a0.y, LOG2E, -mA2))
             + ex2(fmaf(a0.z, LOG2E, -mA2)) + ex2(fmaf(a0.w, LOG2E, -mA2))
             + ex2(fmaf(a1.x, LOG2E, -mA2)) + ex2(fmaf(a1.y, LOG2E, -mA2))
             + ex2(fmaf(a1.z, LOG2E, -mA2)) + ex2(fmaf(a1.w, LOG2E, -mA2));
    float sB = ex2(fmaf(b0.x, LOG2E, -mB2)) + ex2(fmaf(b0.y, LOG2E, -mB2))
             + ex2(fmaf(b0.z, LOG2E, -mB2)) + ex2(fmaf(b0.w, LOG2E, -mB2))
             + ex2(fmaf(b1.x, LOG2E, -mB2)) + ex2(fmaf(b1.y, LOG2E, -mB2))
             + ex2(fmaf(b1.z, LOG2E, -mB2)) + ex2(fmaf(b1.w, LOG2E, -mB2));
#pragma unroll
    for (int o = 16; o; o >>= 1) {
        sA += __shfl_xor_sync(FULLM, sA, o);
        sB += __shfl_xor_sync(FULLM, sB, o);
    }
    float lseA = mA2 + lg2(sA);            // log2(sum exp)
    float lseB = mB2 + lg2(sB);

    float* gA = g_buf + ((size_t)b * TPAD + tA) * GSTR;
    float* gB = g_buf + ((size_t)b * TPAD + tB) * GSTR;
    int l0 = lab[lane], l1 = lab[lane + 32];
    gA[lane]      = ex2(fmaf(rowA[l0], LOG2E, -lseA));   // L1-hit gathers
    gA[lane + 32] = ex2(fmaf(rowA[l1], LOG2E, -lseA));
    gB[lane]      = ex2(fmaf(rowB[l0], LOG2E, -lseB));
    gB[lane + 32] = ex2(fmaf(rowB[l1], LOG2E, -lseB));
    if (lane == 0) {                                      // blank prob, col 64
        gA[64] = ex2(fmaf(rowA[0], LOG2E, -lseA));
        gB[64] = ex2(fmaf(rowB[0], LOG2E, -lseB));
    }
}

// ---------------------------------------------------------------------------
// Kernel 2: linear-domain forward recursion, warp-synchronous, PER-LANE
// exponent tracking. One warp per batch row, 4 states/lane (+state128 lane31).
// One shfl + ~16 FMA-pipe instr per step; rescale every 8 steps.
// ---------------------------------------------------------------------------
__global__ void __launch_bounds__(32, 16)
k_ctc(const int* __restrict__ targets,
      const int* __restrict__ in_len,
      const int* __restrict__ tgt_len) {
    int b    = blockIdx.x;
    int lane = threadIdx.x;

    const float* grow = g_buf + (size_t)b * TPAD * GSTR;
    const float* gl   = grow + 2 * lane;    // this lane's label-pair base
    const float* gb   = grow + 64;          // blank base

    int tA = targets[b * Ll + 2 * lane];        // ext label of state 4lane+1
    int tB = targets[b * Ll + 2 * lane + 1];    // ext label of state 4lane+3
    int tP = __shfl_up_sync(FULLM, tB, 1);      // targets[2lane-1]
    float sk1 = (lane > 0 && tA != tP) ? 1.0f : 0.0f;
    float sk3 = (tB != tA) ? 1.0f : 0.0f;

    float a0 = 0.f, a1 = 0.f, a2 = 0.f, a3 = 0.f, a4 = 0.f;
    if (lane == 0) { a0 = grow[64]; a1 = grow[0]; }   // t=0 init

    int Ti = in_len[b]; if (Ti > Tt) Ti = Tt;
    int nsteps = Ti - 1;
    int E = 0;           // true alpha = reg * 2^E  (per lane)
    float f = 1.0f;      // 2^(E_prevlane - E_thislane), window-constant

    float2 pf2[8]; float pfb[8];
#pragma unroll
    for (int i = 0; i < 8; i++) {
        pf2[i] = *(const float2*)(gl + (1 + i) * GSTR);
        pfb[i] = gb[(1 + i) * GSTR];
    }

#define STEP(PL, PB) do {                                        \
        float n1 = __shfl_up_sync(FULLM, a3, 1) * f;             \
        if (lane == 0) n1 = 0.f;                                 \
        float w0 = (a0 + n1) * (PB);                             \
        float w1 = fmaf(sk1, n1, a1 + a0) * (PL).x;              \
        float w2 = (a2 + a1) * (PB);                             \
        float w3 = fmaf(sk3, a1, a3 + a2) * (PL).y;              \
        float w4 = (a4 + a3) * (PB);                             \
        a0 = w0; a1 = w1; a2 = w2; a3 = w3; a4 = w4;             \
    } while (0)

    int full_iters = nsteps >> 3;
    int t = 1;
    for (int it = 0; it < full_iters; ++it) {
#pragma unroll
        for (int i = 0; i < 8; i++) {
            float2 pl = pf2[i]; float pb = pfb[i];
            pf2[i] = *(const float2*)(gl + (t + 8 + i) * GSTR);  // prefetch
            pfb[i] = gb[(t + 8 + i) * GSTR];
            STEP(pl, pb);
        }
        t += 8;
        // ---- per-lane rescale to exponent 2^64 ----
        float m = fmaxf(fmaxf(a0, a1), fmaxf(a2, a3));
        if (lane == 31) m = fmaxf(m, a4);
        bool act = (m > 0.f);
        int ex = (__float_as_int(m) >> 23) & 255;    // biased exponent
        if (act) {
            int d  = 191 - ex;                       // shift to biased exp 191 (=2^64)
            int d1 = d >> 1, d2 = d - d1;            // split: both within ±126
            float s1 = __int_as_float((d1 + 127) << 23);
            float s2 = __int_as_float((d2 + 127) << 23);
            float sf = s1 * s2;                      // hmm: d<=190 -> sf<=2^190 overflows!
            a0 = (a0 * s1) * s2; a1 = (a1 * s1) * s2;
            a2 = (a2 * s1) * s2; a3 = (a3 * s1) * s2;
            a4 = (a4 * s1) * s2;
            (void)sf;
            E += ex - 191;
        }
        // inactive lanes adopt warp-min of active E (≈ frontier scale)
        int Ec = act ? E : 0x7fffffff;
#pragma unroll
        for (int o = 16; o; o >>= 1) Ec = min(Ec, __shfl_xor_sync(FULLM, Ec, o));
        if (!act) E = Ec;
        // neighbor conversion factor for next window
        int Ep = __shfl_up_sync(FULLM, E, 1);
        int de = Ep - E;
        de = de > 126 ? 126 : (de < -126 ? -126 : de);
        f = __int_as_float((de + 127) << 23);
    }
    int rem = nsteps & 7;
    for (int i = 0; i < rem; i++)          // tail: ring already holds these t's
        STEP(pf2[i], pfb[i]);
#undef STEP

    // publish states + per-lane exponents, lane 0 finishes in log2 domain
    __shared__ float s_a[Ss];
    __shared__ int   s_e[33];
    s_a[4 * lane + 0] = a0; s_a[4 * lane + 1] = a1;
    s_a[4 * lane + 2] = a2; s_a[4 * lane + 3] = a3;
    s_e[lane] = E;
    if (lane == 31) { s_a[128] = a4; s_e[32] = E; }
    __syncwarp();
    if (lane == 0) {
        int tl = tgt_len[b];
        int i1 = 2 * tl, i2 = 2 * tl - 1;
        float r1 = s_a[i1], r2 = s_a[i2];
        float L1 = (r1 > 0.f) ? lg2(r1) + (float)s_e[i1 >> 2] : -3.0e30f;
        float L2 = (r2 > 0.f) ? lg2(r2) + (float)s_e[i2 >> 2] : -3.0e30f;
        float M  = fmaxf(L1, L2);
        float l2v = M + lg2(ex2(L1 - M) + ex2(L2 - M));
        float loss = -l2v * LN2;
        if (!(loss <= 1e20f)) loss = 0.0f;           // zero_infinity (inf/NaN)
        loss_buf[b] = loss / (float)tl;
    }
}

// ---------------------------------------------------------------------------
// Kernel 3: deterministic mean over B=256 (no atomics).
// ---------------------------------------------------------------------------
__global__ void k_reduce(float* __restrict__ out) {
    int i = threadIdx.x;
    float v = loss_buf[i];
#pragma unroll
    for (int o = 16; o; o >>= 1) v += __shfl_xor_sync(FULLM, v, o);
    __shared__ float ws[8];
    if ((i & 31) == 0) ws[i >> 5] = v;
    __syncthreads();
    if (i == 0) {
        float sum = 0.f;
#pragma unroll
        for (int w = 0; w < 8; w++) sum += ws[w];
        out[0] = sum * (1.0f / (float)Bb);
    }
}

extern "C" void kernel_launch(void* const* d_in, const int* in_sizes, int n_in,
                              void* d_out, int out_size) {
    const float* logits  = (const float*)d_in[0];
    const int*   targets = (const int*)d_in[1];
    const int*   in_len  = (const int*)d_in[2];
    const int*   tgt_len = (const int*)d_in[3];
    float* out = (float*)d_out;

    k_lse_gather<<<dim3(32, Bb), 256>>>(logits, targets);
    k_ctc<<<Bb, 32>>>(targets, in_len, tgt_len);
    k_reduce<<<1, 256>>>(out);
}

// round 12
// speedup vs baseline: 2.6830x; 1.5816x over previous
#include <cuda_runtime.h>

#define Bb 256
#define Tt 512
#define Cc 256
#define Ll 64
#define Ss 129             // 2*L+1 extended states
#define GSTR 66            // gather row: cols 0..63 = p(labels), col 64 = p(blank)
#define TPAD 520           // padded T so prefetch can read past the end
#define LOG2E 1.4426950408889634f
#define LN2   0.6931471805599453f
#define FULLM 0xffffffffu

// Hardware MUFU ops — one SASS instruction each
__device__ __forceinline__ float ex2(float x) {
    float r; asm("ex2.approx.ftz.f32 %0, %1;" : "=f"(r) : "f"(x)); return r;
}
__device__ __forceinline__ float lg2(float x) {
    float r; asm("lg2.approx.ftz.f32 %0, %1;" : "=f"(r) : "f"(x)); return r;
}

// scratch (static device globals: allocation-free)
__device__ float g_buf[(size_t)Bb * TPAD * GSTR];   // ~35 MB
__device__ float loss_buf[Bb];

// ---------------------------------------------------------------------------
// Kernel 1: softmax probs (linear domain) of the 65 needed classes per (b,t).
// Warp handles rows t and t+256; the t+256 half is skipped when >= in_len[b].
// ---------------------------------------------------------------------------
__global__ void k_lse_gather(const float* __restrict__ logits,
                             const int* __restrict__ targets,
                             const int* __restrict__ in_len) {
    int b    = blockIdx.y;
    int warp = threadIdx.x >> 5;
    int lane = threadIdx.x & 31;

    __shared__ int lab[Ll];
    if (threadIdx.x < Ll) lab[threadIdx.x] = targets[b * Ll + threadIdx.x];
    __syncthreads();

    int tA = blockIdx.x * 8 + warp;        // 0..255, always < in_len
    int tB = tA + 256;                     // 256..511, maybe past in_len
    bool doB = (tB < in_len[b]);           // warp-uniform

    const float* rowA = logits + ((size_t)b * Tt + tA) * Cc;
    const float* rowB = logits + ((size_t)b * Tt + tB) * Cc;
    const float4* rA = (const float4*)rowA;
    const float4* rB = (const float4*)rowB;
    float4 a0 = rA[lane], a1 = rA[lane + 32];
    float4 b0, b1;
    if (doB) { b0 = rB[lane]; b1 = rB[lane + 32]; }

    int l0 = lab[lane], l1 = lab[lane + 32];

    // ---- A half ----
    float mA = fmaxf(fmaxf(fmaxf(a0.x, a0.y), fmaxf(a0.z, a0.w)),
                     fmaxf(fmaxf(a1.x, a1.y), fmaxf(a1.z, a1.w)));
#pragma unroll
    for (int o = 16; o; o >>= 1) mA = fmaxf(mA, __shfl_xor_sync(FULLM, mA, o));
    float mA2 = mA * LOG2E;
    float sA = ex2(fmaf(a0.x, LOG2E, -mA2)) + ex2(fmaf(a0.y, LOG2E, -mA2))
             + ex2(fmaf(a0.z, LOG2E, -mA2)) + ex2(fmaf(a0.w, LOG2E, -mA2))
             + ex2(fmaf(a1.x, LOG2E, -mA2)) + ex2(fmaf(a1.y, LOG2E, -mA2))
             + ex2(fmaf(a1.z, LOG2E, -mA2)) + ex2(fmaf(a1.w, LOG2E, -mA2));
#pragma unroll
    for (int o = 16; o; o >>= 1) sA += __shfl_xor_sync(FULLM, sA, o);
    float lseA = mA2 + lg2(sA);

    float* gA = g_buf + ((size_t)b * TPAD + tA) * GSTR;
    gA[lane]      = ex2(fmaf(rowA[l0], LOG2E, -lseA));   // L1-hit gathers
    gA[lane + 32] = ex2(fmaf(rowA[l1], LOG2E, -lseA));
    if (lane == 0) gA[64] = ex2(fmaf(rowA[0], LOG2E, -lseA));

    // ---- B half (skipped past input length) ----
    if (doB) {
        float mB = fmaxf(fmaxf(fmaxf(b0.x, b0.y), fmaxf(b0.z, b0.w)),
                         fmaxf(fmaxf(b1.x, b1.y), fmaxf(b1.z, b1.w)));
#pragma unroll
        for (int o = 16; o; o >>= 1) mB = fmaxf(mB, __shfl_xor_sync(FULLM, mB, o));
        float mB2 = mB * LOG2E;
        float sB = ex2(fmaf(b0.x, LOG2E, -mB2)) + ex2(fmaf(b0.y, LOG2E, -mB2))
                 + ex2(fmaf(b0.z, LOG2E, -mB2)) + ex2(fmaf(b0.w, LOG2E, -mB2))
                 + ex2(fmaf(b1.x, LOG2E, -mB2)) + ex2(fmaf(b1.y, LOG2E, -mB2))
                 + ex2(fmaf(b1.z, LOG2E, -mB2)) + ex2(fmaf(b1.w, LOG2E, -mB2));
#pragma unroll
        for (int o = 16; o; o >>= 1) sB += __shfl_xor_sync(FULLM, sB, o);
        float lseB = mB2 + lg2(sB);

        float* gB = g_buf + ((size_t)b * TPAD + tB) * GSTR;
        gB[lane]      = ex2(fmaf(rowB[l0], LOG2E, -lseB));
        gB[lane + 32] = ex2(fmaf(rowB[l1], LOG2E, -lseB));
        if (lane == 0) gB[64] = ex2(fmaf(rowB[0], LOG2E, -lseB));
    }
}

// ---------------------------------------------------------------------------
// Kernel 2: linear-domain forward recursion, warp-synchronous, per-lane
// exponent tracking. One warp per batch row, 4 states/lane (+state128 lane31).
// 16-deep prefetch ring (2 banks of 8, constant indices), rescale every 8
// steps via REDUX.MIN + 1 shfl.
// ---------------------------------------------------------------------------
__global__ void __launch_bounds__(32, 16)
k_ctc(const int* __restrict__ targets,
      const int* __restrict__ in_len,
      const int* __restrict__ tgt_len) {
    int b    = blockIdx.x;
    int lane = threadIdx.x;

    const float* grow = g_buf + (size_t)b * TPAD * GSTR;
    const float* gl   = grow + 2 * lane;    // this lane's label-pair base
    const float* gb   = grow + 64;          // blank base

    int tA = targets[b * Ll + 2 * lane];        // ext label of state 4lane+1
    int tB = targets[b * Ll + 2 * lane + 1];    // ext label of state 4lane+3
    int tP = __shfl_up_sync(FULLM, tB, 1);      // targets[2lane-1]
    float sk1 = (lane > 0 && tA != tP) ? 1.0f : 0.0f;
    float sk3 = (tB != tA) ? 1.0f : 0.0f;

    float a0 = 0.f, a1 = 0.f, a2 = 0.f, a3 = 0.f, a4 = 0.f;
    if (lane == 0) { a0 = grow[64]; a1 = grow[0]; }   // t=0 init

    int Ti = in_len[b]; if (Ti > Tt) Ti = Tt;
    int nsteps = Ti - 1;
    int E = 0;           // true alpha = reg * 2^E  (per lane)
    float f = 1.0f;      // 2^(E_prevlane - E_thislane), window-constant

    // 16-deep prefetch ring, two 8-slot banks (all indices compile-time)
    float2 pf2[16]; float pfb[16];
#pragma unroll
    for (int i = 0; i < 16; i++) {
        pf2[i] = *(const float2*)(gl + (1 + i) * GSTR);
        pfb[i] = gb[(1 + i) * GSTR];
    }

#define STEP(PL, PB) do {                                        \
        float n1 = __shfl_up_sync(FULLM, a3, 1) * f;             \
        if (lane == 0) n1 = 0.f;                                 \
        float w0 = (a0 + n1) * (PB);                             \
        float w1 = fmaf(sk1, n1, a1 + a0) * (PL).x;              \
        float w2 = (a2 + a1) * (PB);                             \
        float w3 = fmaf(sk3, a1, a3 + a2) * (PL).y;              \
        float w4 = (a4 + a3) * (PB);                             \
        a0 = w0; a1 = w1; a2 = w2; a3 = w3; a4 = w4;             \
    } while (0)

#define RESCALE do {                                                       \
        float m = fmaxf(fmaxf(a0, a1), fmaxf(a2, a3));                     \
        if (lane == 31) m = fmaxf(m, a4);                                  \
        bool act = (m > 0.f);                                              \
        int ex = (__float_as_int(m) >> 23) & 255;                          \
        if (act) {                                                         \
            int d  = 191 - ex;          /* rescale lane max to 2^64 */     \
            int d1 = d >> 1, d2 = d - d1;                                  \
            float s1 = __int_as_float((d1 + 127) << 23);                   \
            float s2 = __int_as_float((d2 + 127) << 23);                   \
            a0 = (a0 * s1) * s2; a1 = (a1 * s1) * s2;                      \
            a2 = (a2 * s1) * s2; a3 = (a3 * s1) * s2;                      \
            a4 = (a4 * s1) * s2;                                           \
            E += ex - 191;                                                 \
        }                                                                  \
        int Ec = act ? E : 0x7fffffff;                                     \
        Ec = __reduce_min_sync(FULLM, Ec);                                 \
        if (!act) E = Ec;                                                  \
        int Ep = __shfl_up_sync(FULLM, E, 1);                              \
        int de = Ep - E;                                                   \
        de = de > 126 ? 126 : (de < -126 ? -126 : de);                     \
        f = __int_as_float((de + 127) << 23);                              \
    } while (0)

    int nblk = nsteps >> 4;     // 16-step blocks (two 8-step windows)
    int t = 1;
    for (int it = 0; it < nblk; ++it) {
#pragma unroll
        for (int i = 0; i < 8; i++) {
            float2 pl = pf2[i]; float pb = pfb[i];
            pf2[i] = *(const float2*)(gl + (t + 16 + i) * GSTR);
            pfb[i] = gb[(t + 16 + i) * GSTR];
            STEP(pl, pb);
        }
        t += 8;
        RESCALE;
#pragma unroll
        for (int i = 0; i < 8; i++) {
            float2 pl = pf2[8 + i]; float pb = pfb[8 + i];
            pf2[8 + i] = *(const float2*)(gl + (t + 16 + i) * GSTR);
            pfb[8 + i] = gb[(t + 16 + i) * GSTR];
            STEP(pl, pb);
        }
        t += 8;
        RESCALE;
    }
    int rem = nsteps & 15;      // tail: ring already holds these steps
#pragma unroll
    for (int i = 0; i < 8; i++)
        if (i < rem) STEP(pf2[i], pfb[i]);
    RESCALE;
#pragma unroll
    for (int i = 0; i < 8; i++)
        if (i + 8 < rem) STEP(pf2[8 + i], pfb[8 + i]);
#undef STEP
#undef RESCALE

    // publish states + per-lane exponents, lane 0 finishes in log2 domain
    __shared__ float s_a[Ss];
    __shared__ int   s_e[33];
    s_a[4 * lane + 0] = a0; s_a[4 * lane + 1] = a1;
    s_a[4 * lane + 2] = a2; s_a[4 * lane + 3] = a3;
    s_e[lane] = E;
    if (lane == 31) { s_a[128] = a4; s_e[32] = E; }
    __syncwarp();
    if (lane == 0) {
        int tl = tgt_len[b];
        int i1 = 2 * tl, i2 = 2 * tl - 1;
        float r1 = s_a[i1], r2 = s_a[i2];
        float L1 = (r1 > 0.f) ? lg2(r1) + (float)s_e[i1 >> 2] : -3.0e30f;
        float L2 = (r2 > 0.f) ? lg2(r2) + (float)s_e[i2 >> 2] : -3.0e30f;
        float M  = fmaxf(L1, L2);
        float l2v = M + lg2(ex2(L1 - M) + ex2(L2 - M));
        float loss = -l2v * LN2;
        if (!(loss <= 1e20f)) loss = 0.0f;           // zero_infinity (inf/NaN)
        loss_buf[b] = loss / (float)tl;
    }
}

// ---------------------------------------------------------------------------
// Kernel 3: deterministic mean over B=256 (no atomics).
// ---------------------------------------------------------------------------
__global__ void k_reduce(float* __restrict__ out) {
    int i = threadIdx.x;
    float v = loss_buf[i];
#pragma unroll
    for (int o = 16; o; o >>= 1) v += __shfl_xor_sync(FULLM, v, o);
    __shared__ float ws[8];
    if ((i & 31) == 0) ws[i >> 5] = v;
    __syncthreads();
    if (i == 0) {
        float sum = 0.f;
#pragma unroll
        for (int w = 0; w < 8; w++) sum += ws[w];
        out[0] = sum * (1.0f / (float)Bb);
    }
}

extern "C" void kernel_launch(void* const* d_in, const int* in_sizes, int n_in,
                              void* d_out, int out_size) {
    const float* logits  = (const float*)d_in[0];
    const int*   targets = (const int*)d_in[1];
    const int*   in_len  = (const int*)d_in[2];
    const int*   tgt_len = (const int*)d_in[3];
    float* out = (float*)d_out;

    k_lse_gather<<<dim3(32, Bb), 256>>>(logits, targets, in_len);
    k_ctc<<<Bb, 32>>>(targets, in_len, tgt_len);
    k_reduce<<<1, 256>>>(out);
}